// round 8
// baseline (speedup 1.0000x reference)
#include <cuda_runtime.h>
#include <math.h>

// Shapes (fixed by the problem)
#define B_ 64
#define S_ 2048
#define H_ 1024
#define E_ 512
#define V_ 50257

// ---------------------------------------------------------------------------
// Device scratch (allocation-free: __device__ globals).
// ---------------------------------------------------------------------------
__device__ float g_gi_part[4 * B_ * 3 * H_];          // 4 K-splits of x @ w_ih^T
__device__ float g_gh_part[4 * B_ * 3 * H_];          // 4 K-splits of h @ w_hh^T
__device__ float g_cat_part[8 * B_ * H_];             // 8 K-splits of concat GEMM
__device__ float g_concat_in[B_ * 2 * H_];            // [h_new | context]
__device__ float g_concat_out[B_ * H_];               // tanh(concat @ Wc^T + bc)
__device__ float g_energies[B_ * S_];                 // raw attention logits
__device__ float2 g_ml[B_ * 128];                     // per-partial (max, sumexp)
__device__ float g_ctxp[(size_t)B_ * 128 * H_];       // per-partial context (32 MB)
__device__ float g_Mv[B_];
__device__ float g_Lv[B_];

// ---------------------------------------------------------------------------
// Small-GEMM path (M=64, modest N): SIMT fp32, K-split partials.
// ---------------------------------------------------------------------------
__global__ __launch_bounds__(256) void gemm64(
    const float* __restrict__ A, const float* __restrict__ Bw,
    float* __restrict__ C, int N, int K, int klen,
    const float* __restrict__ bias, int act)
{
    __shared__ float As[16][64];
    __shared__ float Bs[16][64];
    const int tid = threadIdx.x;
    const int tx = tid & 15, ty = tid >> 4;
    const int n0 = blockIdx.x * 64;
    const int k0 = blockIdx.y * klen;
    C += (size_t)blockIdx.y * 64 * N;

    const int a_r = tid >> 2;
    const int a_c = (tid & 3) << 2;

    float acc[4][4];
#pragma unroll
    for (int i = 0; i < 4; i++)
#pragma unroll
        for (int j = 0; j < 4; j++) acc[i][j] = 0.f;

    for (int kk0 = 0; kk0 < klen; kk0 += 16) {
        const int kb = k0 + kk0 + a_c;
        float4 av = *(const float4*)(A + (size_t)a_r * K + kb);
        float4 bv = make_float4(0.f, 0.f, 0.f, 0.f);
        const int nr = n0 + a_r;
        if (nr < N) bv = *(const float4*)(Bw + (size_t)nr * K + kb);

        __syncthreads();
        As[a_c + 0][a_r] = av.x; As[a_c + 1][a_r] = av.y;
        As[a_c + 2][a_r] = av.z; As[a_c + 3][a_r] = av.w;
        Bs[a_c + 0][a_r] = bv.x; Bs[a_c + 1][a_r] = bv.y;
        Bs[a_c + 2][a_r] = bv.z; Bs[a_c + 3][a_r] = bv.w;
        __syncthreads();

#pragma unroll
        for (int kk = 0; kk < 16; kk++) {
            float4 a  = *(const float4*)&As[kk][ty << 2];
            float4 bb = *(const float4*)&Bs[kk][tx << 2];
            float am[4] = {a.x, a.y, a.z, a.w};
            float bn[4] = {bb.x, bb.y, bb.z, bb.w};
#pragma unroll
            for (int i = 0; i < 4; i++)
#pragma unroll
                for (int j = 0; j < 4; j++)
                    acc[i][j] = fmaf(am[i], bn[j], acc[i][j]);
        }
    }

#pragma unroll
    for (int i = 0; i < 4; i++) {
        const int m = (ty << 2) + i;
#pragma unroll
        for (int j = 0; j < 4; j++) {
            const int n = n0 + (tx << 2) + j;
            if (n < N) {
                float v = acc[i][j];
                if (bias) v += bias[n];
                if (act) v = tanhf(v);
                C[(size_t)m * N + n] = v;
            }
        }
    }
}

// ---------------------------------------------------------------------------
// Output GEMM: C[64, V] = A[64, 1024] * Wo[V, 1024]^T + bias, tf32 tensor cores.
// CTA tile 64x128, 8 warps (2M x 4N), mma.sync m16n8k8 tf32.
// K-chunks of 16, cp.async 3-stage pipeline (2 chunks in flight/CTA, 2 CTAs/SM
// -> 4 outstanding B-tile loads per SM, DRAM latency fully hidden).
// SMEM rows padded to 20 floats (stride 20 mod 32 -> g*20 hits 8 distinct bank
// groups: conflict-free fragment loads).
// ---------------------------------------------------------------------------
__device__ __forceinline__ void cp_async16(void* dst, const void* src) {
    unsigned d = (unsigned)__cvta_generic_to_shared(dst);
    asm volatile("cp.async.ca.shared.global [%0], [%1], 16;" :: "r"(d), "l"(src));
}
__device__ __forceinline__ void cp_commit() {
    asm volatile("cp.async.commit_group;");
}
template <int N> __device__ __forceinline__ void cp_wait() {
    asm volatile("cp.async.wait_group %0;" :: "n"(N));
}
__device__ __forceinline__ unsigned f2tf(float x) {
    unsigned r;
    asm("cvt.rna.tf32.f32 %0, %1;" : "=r"(r) : "f"(x));
    return r;
}
__device__ __forceinline__ void mma_tf32(float4& c, const unsigned a[4],
                                         unsigned b0, unsigned b1) {
    asm volatile(
        "mma.sync.aligned.m16n8k8.row.col.f32.tf32.tf32.f32 "
        "{%0,%1,%2,%3}, {%4,%5,%6,%7}, {%8,%9}, {%0,%1,%2,%3};"
        : "+f"(c.x), "+f"(c.y), "+f"(c.z), "+f"(c.w)
        : "r"(a[0]), "r"(a[1]), "r"(a[2]), "r"(a[3]), "r"(b0), "r"(b1));
}

__global__ __launch_bounds__(256, 2) void out_gemm_tf32(
    const float* __restrict__ A,    // [64, 1024]
    const float* __restrict__ Bw,   // [V, 1024]
    const float* __restrict__ bias, // [V]
    float* __restrict__ C)          // [64, V]
{
    __shared__ float As[3][64][20];     // 3-stage: 46080 B total (static-smem OK)
    __shared__ float Bs[3][128][20];
    const int tid = threadIdx.x;
    const int lane = tid & 31, warp = tid >> 5;
    const int g = lane >> 2, tig = lane & 3;
    const int wm = warp & 1, wn = warp >> 1;
    const int n_base = blockIdx.x * 128;

    const int srow = tid >> 2;          // 0..63
    const int sf   = (tid & 3) << 2;    // 0,4,8,12

    float4 acc[2][4];
#pragma unroll
    for (int f = 0; f < 2; f++)
#pragma unroll
        for (int j = 0; j < 4; j++) acc[f][j] = make_float4(0.f, 0.f, 0.f, 0.f);

#define STAGE(buf, ch) do {                                                        \
        cp_async16(&As[buf][srow][sf], A + (size_t)srow * 1024 + (ch) * 16 + sf);  \
        const int n0s = n_base + srow;                                             \
        if (n0s < V_)                                                              \
            cp_async16(&Bs[buf][srow][sf],                                         \
                       Bw + (size_t)n0s * 1024 + (ch) * 16 + sf);                  \
        const int n1s = n_base + 64 + srow;                                        \
        if (n1s < V_)                                                              \
            cp_async16(&Bs[buf][64 + srow][sf],                                    \
                       Bw + (size_t)n1s * 1024 + (ch) * 16 + sf);                  \
        cp_commit();                                                               \
    } while (0)

    STAGE(0, 0);
    STAGE(1, 1);

    for (int c = 0; c < 64; c++) {
        const int buf = c - (c / 3) * 3;              // c % 3
        if (c + 2 < 64) {
            const int nb = (c + 2) - ((c + 2) / 3) * 3;
            STAGE(nb, c + 2);
            cp_wait<2>();                              // chunk c complete
        } else if (c + 1 < 64) {
            cp_wait<1>();
        } else {
            cp_wait<0>();
        }
        __syncthreads();

#pragma unroll
        for (int s = 0; s < 2; s++) {
            const int ks = s * 8;
            unsigned ua[2][4];
#pragma unroll
            for (int f = 0; f < 2; f++) {
                const int m0 = wm * 32 + f * 16;
                ua[f][0] = f2tf(As[buf][m0 + g][ks + tig]);
                ua[f][1] = f2tf(As[buf][m0 + g + 8][ks + tig]);
                ua[f][2] = f2tf(As[buf][m0 + g][ks + tig + 4]);
                ua[f][3] = f2tf(As[buf][m0 + g + 8][ks + tig + 4]);
            }
#pragma unroll
            for (int j = 0; j < 4; j++) {
                const int n0 = wn * 32 + j * 8;
                const unsigned b0 = f2tf(Bs[buf][n0 + g][ks + tig]);
                const unsigned b1 = f2tf(Bs[buf][n0 + g][ks + tig + 4]);
                mma_tf32(acc[0][j], ua[0], b0, b1);
                mma_tf32(acc[1][j], ua[1], b0, b1);
            }
        }
        __syncthreads();
    }
#undef STAGE

#pragma unroll
    for (int f = 0; f < 2; f++) {
        const int r0 = wm * 32 + f * 16 + g;
#pragma unroll
        for (int j = 0; j < 4; j++) {
            const int col = n_base + wn * 32 + j * 8 + tig * 2;
            const float4 v = acc[f][j];
            if (col + 1 < V_) {
                const float bv0 = bias[col], bv1 = bias[col + 1];
                C[(size_t)r0 * V_ + col]           = v.x + bv0;
                C[(size_t)r0 * V_ + col + 1]       = v.y + bv1;
                C[(size_t)(r0 + 8) * V_ + col]     = v.z + bv0;
                C[(size_t)(r0 + 8) * V_ + col + 1] = v.w + bv1;
            } else if (col < V_) {
                const float bv0 = bias[col];
                C[(size_t)r0 * V_ + col]       = v.x + bv0;
                C[(size_t)(r0 + 8) * V_ + col] = v.z + bv0;
            }
        }
    }
}

// ---------------------------------------------------------------------------
// GRU gate math.
// ---------------------------------------------------------------------------
__global__ void gru_gates(const float* __restrict__ b_ih,
                          const float* __restrict__ b_hh,
                          const float* __restrict__ hprev,
                          float* __restrict__ out_hidden)
{
    const int idx = blockIdx.x * blockDim.x + threadIdx.x;   // < B*H
    const int b = idx >> 10, h = idx & (H_ - 1);
    float gir = b_ih[h], giz = b_ih[H_ + h], gin = b_ih[2 * H_ + h];
    float ghr = b_hh[h], ghz = b_hh[H_ + h], ghn = b_hh[2 * H_ + h];
#pragma unroll
    for (int p = 0; p < 4; p++) {
        const float* gi = g_gi_part + (size_t)p * (B_ * 3 * H_) + (size_t)b * 3 * H_;
        const float* gh = g_gh_part + (size_t)p * (B_ * 3 * H_) + (size_t)b * 3 * H_;
        gir += gi[h];          ghr += gh[h];
        giz += gi[H_ + h];     ghz += gh[H_ + h];
        gin += gi[2 * H_ + h]; ghn += gh[2 * H_ + h];
    }
    const float r = 1.f / (1.f + expf(-(gir + ghr)));
    const float z = 1.f / (1.f + expf(-(giz + ghz)));
    const float n = tanhf(gin + r * ghn);
    const float hn = (1.f - z) * n + z * hprev[idx];
    g_concat_in[(size_t)b * 2 * H_ + h] = hn;
    out_hidden[idx] = hn;
}

// ---------------------------------------------------------------------------
// Flash-style attention: one pass over encoder_outputs (512 MB), per-warp
// online softmax + register-resident H=1024 context accumulator.
// ---------------------------------------------------------------------------
__global__ __launch_bounds__(256, 1) void flash_attn(const float* __restrict__ enc)
{
    const int b = blockIdx.y;
    const int chunk = blockIdx.x;
    __shared__ float sh[H_];
    const int t = threadIdx.x;
    *(float4*)&sh[t * 4] = *(const float4*)&g_concat_in[(size_t)b * 2 * H_ + t * 4];
    __syncthreads();

    const int warp = t >> 5, lane = t & 31;
    float4 hn[8];
#pragma unroll
    for (int i = 0; i < 8; i++) hn[i] = *(const float4*)&sh[i * 128 + lane * 4];

    float m = -INFINITY, l = 0.f;
    float4 cv[8];
#pragma unroll
    for (int i = 0; i < 8; i++) cv[i] = make_float4(0.f, 0.f, 0.f, 0.f);

    const int sbase = chunk * 128 + warp * 16;
    for (int si = 0; si < 16; si++) {
        const int s = sbase + si;
        const float4* ep = (const float4*)(enc + ((size_t)s * B_ + b) * H_);
        float4 ev[8];
        float d = 0.f;
#pragma unroll
        for (int i = 0; i < 8; i++) {
            ev[i] = ep[i * 32 + lane];
            d = fmaf(ev[i].x, hn[i].x, d);
            d = fmaf(ev[i].y, hn[i].y, d);
            d = fmaf(ev[i].z, hn[i].z, d);
            d = fmaf(ev[i].w, hn[i].w, d);
        }
#pragma unroll
        for (int off = 16; off; off >>= 1)
            d += __shfl_xor_sync(0xffffffffu, d, off);

        if (lane == 0) g_energies[(size_t)b * S_ + s] = d;

        const float mn = fmaxf(m, d);
        const float sc = expf(m - mn);
        const float p  = expf(d - mn);
        l = l * sc + p;
#pragma unroll
        for (int i = 0; i < 8; i++) {
            cv[i].x = fmaf(p, ev[i].x, cv[i].x * sc);
            cv[i].y = fmaf(p, ev[i].y, cv[i].y * sc);
            cv[i].z = fmaf(p, ev[i].z, cv[i].z * sc);
            cv[i].w = fmaf(p, ev[i].w, cv[i].w * sc);
        }
        m = mn;
    }

    const int pi = chunk * 8 + warp;
    if (lane == 0) g_ml[b * 128 + pi] = make_float2(m, l);
    float4* cp = (float4*)(g_ctxp + ((size_t)(b * 128 + pi)) * H_);
#pragma unroll
    for (int i = 0; i < 8; i++) cp[i * 32 + lane] = cv[i];
}

// ---------------------------------------------------------------------------
// Combine softmax partials. grid = (4, B), 64 threads: each CTA owns 256
// contiguous H-floats (one float4 per thread). Unroll 8 -> MLP 8 on the
// 32 MB partial read.
// ---------------------------------------------------------------------------
__global__ void attn_combine()
{
    const int b = blockIdx.y, q = blockIdx.x, t = threadIdx.x;  // t < 64
    __shared__ float sw[128];
    __shared__ float red[64];

    const float2 ml0 = g_ml[b * 128 + t];
    const float2 ml1 = g_ml[b * 128 + 64 + t];

    red[t] = fmaxf(ml0.x, ml1.x);
    __syncthreads();
    for (int off = 32; off >= 1; off >>= 1) {
        if (t < off) red[t] = fmaxf(red[t], red[t + off]);
        __syncthreads();
    }
    const float M = red[0];
    __syncthreads();

    const float w0 = expf(ml0.x - M), w1 = expf(ml1.x - M);
    sw[t] = w0; sw[64 + t] = w1;
    red[t] = ml0.y * w0 + ml1.y * w1;
    __syncthreads();
    for (int off = 32; off >= 1; off >>= 1) {
        if (t < off) red[t] += red[t + off];
        __syncthreads();
    }
    const float L = red[0];

    float4 acc = make_float4(0.f, 0.f, 0.f, 0.f);
    const float4* base = (const float4*)(g_ctxp + (size_t)b * 128 * H_) + q * 64 + t;
#pragma unroll 8
    for (int p = 0; p < 128; p++) {
        const float f = sw[p];
        const float4 v = base[(size_t)p * (H_ / 4)];
        acc.x = fmaf(f, v.x, acc.x);
        acc.y = fmaf(f, v.y, acc.y);
        acc.z = fmaf(f, v.z, acc.z);
        acc.w = fmaf(f, v.w, acc.w);
    }
    const float inv = 1.f / L;
    acc.x *= inv; acc.y *= inv; acc.z *= inv; acc.w *= inv;
    *(float4*)&g_concat_in[(size_t)b * 2 * H_ + H_ + (q * 64 + t) * 4] = acc;
    if (q == 0 && t == 0) { g_Mv[b] = M; g_Lv[b] = L; }
}

// attn_weights output
__global__ void attn_weights_out(float* __restrict__ out_attn)
{
    const int idx = blockIdx.x * blockDim.x + threadIdx.x;   // < B*S
    const int b = idx >> 11;
    out_attn[idx] = expf(g_energies[idx] - g_Mv[b]) / g_Lv[b];
}

// Sum concat-GEMM K-split partials, add bias, tanh.
__global__ void cat_finalize(const float* __restrict__ b_concat)
{
    const int idx = blockIdx.x * blockDim.x + threadIdx.x;   // < B*H
    float v = b_concat[idx & (H_ - 1)];
#pragma unroll
    for (int p = 0; p < 8; p++) v += g_cat_part[(size_t)p * (B_ * H_) + idx];
    g_concat_out[idx] = tanhf(v);
}

// ---------------------------------------------------------------------------
extern "C" void kernel_launch(void* const* d_in, const int* in_sizes, int n_in,
                              void* d_out, int out_size)
{
    (void)in_sizes; (void)n_in; (void)out_size;
    const float* x    = (const float*)d_in[0];
    const float* h0   = (const float*)d_in[1];
    const float* enc  = (const float*)d_in[2];
    const float* w_ih = (const float*)d_in[3];
    const float* w_hh = (const float*)d_in[4];
    const float* b_ih = (const float*)d_in[5];
    const float* b_hh = (const float*)d_in[6];
    const float* Wc   = (const float*)d_in[7];
    const float* bc   = (const float*)d_in[8];
    const float* Wo   = (const float*)d_in[9];
    const float* bo   = (const float*)d_in[10];

    float* out        = (float*)d_out;
    float* out_output = out;                              // [B,V]
    float* out_hidden = out + (size_t)B_ * V_;            // [1,B,H]
    float* out_attn   = out_hidden + (size_t)B_ * H_;     // [B,1,S]

    void *p_gi, *p_gh, *p_cat, *p_cin, *p_cout;
    cudaGetSymbolAddress(&p_gi,  g_gi_part);
    cudaGetSymbolAddress(&p_gh,  g_gh_part);
    cudaGetSymbolAddress(&p_cat, g_cat_part);
    cudaGetSymbolAddress(&p_cin, g_concat_in);
    cudaGetSymbolAddress(&p_cout, g_concat_out);

    // GRU input/hidden GEMMs (K-split x4)
    gemm64<<<dim3(48, 4), 256>>>(x,  w_ih, (float*)p_gi, 3 * H_, E_, E_ / 4, nullptr, 0);
    gemm64<<<dim3(48, 4), 256>>>(h0, w_hh, (float*)p_gh, 3 * H_, H_, H_ / 4, nullptr, 0);
    gru_gates<<<(B_ * H_) / 256, 256>>>(b_ih, b_hh, h0, out_hidden);

    // One-pass attention + split-softmax combine
    flash_attn<<<dim3(16, B_), 256>>>(enc);
    attn_combine<<<dim3(4, B_), 64>>>();
    attn_weights_out<<<(B_ * S_) / 256, 256>>>(out_attn);

    // concat projection (K-split x8) + tanh
    gemm64<<<dim3(16, 8), 256>>>((const float*)p_cin, Wc, (float*)p_cat,
                                 H_, 2 * H_, 256, nullptr, 0);
    cat_finalize<<<(B_ * H_) / 256, 256>>>(bc);

    // Output GEMM: 64 x 50257 x 1024 (+bias), tf32 tensor cores, 393 CTAs
    out_gemm_tf32<<<(V_ + 127) / 128, 256>>>((const float*)p_cout, Wo, bo, out_output);
}

// round 9
// speedup vs baseline: 1.0646x; 1.0646x over previous
#include <cuda_runtime.h>
#include <cuda.h>
#include <math.h>

// Shapes (fixed by the problem)
#define B_ 64
#define S_ 2048
#define H_ 1024
#define E_ 512
#define V_ 50257

// ---------------------------------------------------------------------------
// Device scratch (allocation-free: __device__ globals).
// ---------------------------------------------------------------------------
__device__ float g_gi_part[4 * B_ * 3 * H_];          // 4 K-splits of x @ w_ih^T
__device__ float g_gh_part[4 * B_ * 3 * H_];          // 4 K-splits of h @ w_hh^T
__device__ float g_cat_part[8 * B_ * H_];             // 8 K-splits of concat GEMM
__device__ float g_concat_in[B_ * 2 * H_];            // [h_new | context]
__device__ float g_concat_out[B_ * H_];               // tanh(concat @ Wc^T + bc)
__device__ float g_energies[B_ * S_];                 // raw attention logits
__device__ float2 g_ml[B_ * 128];                     // per-partial (max, sumexp)
__device__ float g_ctxp[(size_t)B_ * 128 * H_];       // per-partial context (32 MB)
__device__ float g_Mv[B_];
__device__ float g_Lv[B_];

// ---------------------------------------------------------------------------
// Small-GEMM path (M=64, modest N): SIMT fp32, K-split partials.
// ---------------------------------------------------------------------------
__global__ __launch_bounds__(256) void gemm64(
    const float* __restrict__ A, const float* __restrict__ Bw,
    float* __restrict__ C, int N, int K, int klen,
    const float* __restrict__ bias, int act)
{
    __shared__ float As[16][64];
    __shared__ float Bs[16][64];
    const int tid = threadIdx.x;
    const int tx = tid & 15, ty = tid >> 4;
    const int n0 = blockIdx.x * 64;
    const int k0 = blockIdx.y * klen;
    C += (size_t)blockIdx.y * 64 * N;

    const int a_r = tid >> 2;
    const int a_c = (tid & 3) << 2;

    float acc[4][4];
#pragma unroll
    for (int i = 0; i < 4; i++)
#pragma unroll
        for (int j = 0; j < 4; j++) acc[i][j] = 0.f;

    for (int kk0 = 0; kk0 < klen; kk0 += 16) {
        const int kb = k0 + kk0 + a_c;
        float4 av = *(const float4*)(A + (size_t)a_r * K + kb);
        float4 bv = make_float4(0.f, 0.f, 0.f, 0.f);
        const int nr = n0 + a_r;
        if (nr < N) bv = *(const float4*)(Bw + (size_t)nr * K + kb);

        __syncthreads();
        As[a_c + 0][a_r] = av.x; As[a_c + 1][a_r] = av.y;
        As[a_c + 2][a_r] = av.z; As[a_c + 3][a_r] = av.w;
        Bs[a_c + 0][a_r] = bv.x; Bs[a_c + 1][a_r] = bv.y;
        Bs[a_c + 2][a_r] = bv.z; Bs[a_c + 3][a_r] = bv.w;
        __syncthreads();

#pragma unroll
        for (int kk = 0; kk < 16; kk++) {
            float4 a  = *(const float4*)&As[kk][ty << 2];
            float4 bb = *(const float4*)&Bs[kk][tx << 2];
            float am[4] = {a.x, a.y, a.z, a.w};
            float bn[4] = {bb.x, bb.y, bb.z, bb.w};
#pragma unroll
            for (int i = 0; i < 4; i++)
#pragma unroll
                for (int j = 0; j < 4; j++)
                    acc[i][j] = fmaf(am[i], bn[j], acc[i][j]);
        }
    }

#pragma unroll
    for (int i = 0; i < 4; i++) {
        const int m = (ty << 2) + i;
#pragma unroll
        for (int j = 0; j < 4; j++) {
            const int n = n0 + (tx << 2) + j;
            if (n < N) {
                float v = acc[i][j];
                if (bias) v += bias[n];
                if (act) v = tanhf(v);
                C[(size_t)m * N + n] = v;
            }
        }
    }
}

// ---------------------------------------------------------------------------
// Shared helpers for the tf32 output GEMM.
// ---------------------------------------------------------------------------
__device__ __forceinline__ void cp_async16(void* dst, const void* src) {
    unsigned d = (unsigned)__cvta_generic_to_shared(dst);
    asm volatile("cp.async.ca.shared.global [%0], [%1], 16;" :: "r"(d), "l"(src));
}
__device__ __forceinline__ void cp_commit() {
    asm volatile("cp.async.commit_group;");
}
template <int N> __device__ __forceinline__ void cp_wait() {
    asm volatile("cp.async.wait_group %0;" :: "n"(N));
}
__device__ __forceinline__ unsigned f2tf(float x) {
    unsigned r;
    asm("cvt.rna.tf32.f32 %0, %1;" : "=r"(r) : "f"(x));
    return r;
}
__device__ __forceinline__ void mma_tf32(float4& c, const unsigned a[4],
                                         unsigned b0, unsigned b1) {
    asm volatile(
        "mma.sync.aligned.m16n8k8.row.col.f32.tf32.tf32.f32 "
        "{%0,%1,%2,%3}, {%4,%5,%6,%7}, {%8,%9}, {%0,%1,%2,%3};"
        : "+f"(c.x), "+f"(c.y), "+f"(c.z), "+f"(c.w)
        : "r"(a[0]), "r"(a[1]), "r"(a[2]), "r"(a[3]), "r"(b0), "r"(b1));
}

// mbarrier / TMA primitives
__device__ __forceinline__ void mbar_init(unsigned a, unsigned cnt) {
    asm volatile("mbarrier.init.shared.b64 [%0], %1;" :: "r"(a), "r"(cnt) : "memory");
}
__device__ __forceinline__ void mbar_expect_tx(unsigned a, unsigned bytes) {
    asm volatile("mbarrier.arrive.expect_tx.shared.b64 _, [%0], %1;"
                 :: "r"(a), "r"(bytes) : "memory");
}
__device__ __forceinline__ void mbar_arrive(unsigned a) {
    asm volatile("mbarrier.arrive.shared.b64 _, [%0];" :: "r"(a) : "memory");
}
__device__ __forceinline__ void mbar_wait(unsigned a, unsigned ph) {
    asm volatile(
        "{\n\t.reg .pred P;\n"
        "WL%=:\n\t"
        "mbarrier.try_wait.parity.acquire.cta.shared::cta.b64 P, [%0], %1, 0x989680;\n\t"
        "@P bra WD%=;\n\t"
        "bra WL%=;\n"
        "WD%=:\n\t}"
        :: "r"(a), "r"(ph) : "memory");
}
__device__ __forceinline__ void tma2d(unsigned dst, const CUtensorMap* m,
                                      int x, int y, unsigned bar) {
    asm volatile(
        "cp.async.bulk.tensor.2d.shared::cta.global.tile.mbarrier::complete_tx::bytes "
        "[%0], [%1, {%2, %3}], [%4];"
        :: "r"(dst), "l"(m), "r"(x), "r"(y), "r"(bar) : "memory");
}

// ---------------------------------------------------------------------------
// TMA-fed output GEMM: C[64, V] = A[64,1024] * Wo[V,1024]^T + bias.
// CTA tile 64x128, 8 warps (2M x 4N), mma.sync m16n8k8 tf32.
// K-chunk 32 (=128B inner box, SWIZZLE_128B), 3-stage mbarrier pipeline.
// Per chunk: ONE TMA for A (8KB) + ONE for B (16KB) — issue cost ~0 vs the
// 768 cp.async ops/chunk that bound the previous version.
// SW128 fragment index: float_idx = row*32 + (k ^ (g<<2)) — conflict-free.
// ---------------------------------------------------------------------------
#define TMA_STAGES 3
#define TMA_ABYTES 8192
#define TMA_BBYTES 16384
#define TMA_SMEM (TMA_STAGES * (TMA_ABYTES + TMA_BBYTES) + 64)

__global__ __launch_bounds__(256, 2) void out_gemm_tma(
    const __grid_constant__ CUtensorMap tmA,
    const __grid_constant__ CUtensorMap tmB,
    const float* __restrict__ bias, float* __restrict__ C)
{
    extern __shared__ __align__(1024) char smem[];
    float* Abuf = (float*)smem;                               // 3 x 8KB
    float* Bbuf = (float*)(smem + TMA_STAGES * TMA_ABYTES);   // 3 x 16KB
    const unsigned sb = (unsigned)__cvta_generic_to_shared(smem);
    const unsigned a_sb = sb;
    const unsigned b_sb = sb + TMA_STAGES * TMA_ABYTES;
    const unsigned mb = sb + TMA_STAGES * (TMA_ABYTES + TMA_BBYTES);
    // full[s] = mb + s*8 ; empty[s] = mb + 24 + s*8

    const int tid = threadIdx.x;
    const int lane = tid & 31, warp = tid >> 5;
    const int g = lane >> 2, tig = lane & 3, gx = g << 2;
    const int wm = warp & 1, wn = warp >> 1;
    const int n_base = blockIdx.x * 128;

    if (tid == 0) {
#pragma unroll
        for (int s = 0; s < TMA_STAGES; s++) {
            mbar_init(mb + s * 8, 1);          // full: TMA tx-based
            mbar_init(mb + 24 + s * 8, 256);   // empty: all threads arrive
        }
        asm volatile("prefetch.tensormap [%0];" :: "l"(&tmA));
        asm volatile("prefetch.tensormap [%0];" :: "l"(&tmB));
    }
    asm volatile("fence.proxy.async.shared::cta;" ::: "memory");
    __syncthreads();

    if (tid == 0) {
#pragma unroll
        for (int s = 0; s < TMA_STAGES; s++) {
            mbar_expect_tx(mb + s * 8, TMA_ABYTES + TMA_BBYTES);
            tma2d(a_sb + s * TMA_ABYTES, &tmA, s * 32, 0,      mb + s * 8);
            tma2d(b_sb + s * TMA_BBYTES, &tmB, s * 32, n_base, mb + s * 8);
        }
    }

    float4 acc[2][4];
#pragma unroll
    for (int f = 0; f < 2; f++)
#pragma unroll
        for (int j = 0; j < 4; j++) acc[f][j] = make_float4(0.f, 0.f, 0.f, 0.f);

    for (int c = 0; c < 32; c++) {
        const int u = c / 3;
        const int s = c - u * 3;
        mbar_wait(mb + s * 8, (unsigned)(u & 1));

        const float* As_s = Abuf + s * (TMA_ABYTES / 4);
        const float* Bs_s = Bbuf + s * (TMA_BBYTES / 4);

#pragma unroll
        for (int ks4 = 0; ks4 < 4; ks4++) {
            const int ks = ks4 * 8;
            const int k0i = (ks + tig) ^ gx;
            const int k1i = (ks + tig + 4) ^ gx;
            unsigned ua[2][4];
#pragma unroll
            for (int f = 0; f < 2; f++) {
                const int m0 = wm * 32 + f * 16;
                ua[f][0] = f2tf(As_s[(m0 + g) * 32 + k0i]);
                ua[f][1] = f2tf(As_s[(m0 + g + 8) * 32 + k0i]);
                ua[f][2] = f2tf(As_s[(m0 + g) * 32 + k1i]);
                ua[f][3] = f2tf(As_s[(m0 + g + 8) * 32 + k1i]);
            }
#pragma unroll
            for (int j = 0; j < 4; j++) {
                const int n0 = wn * 32 + j * 8;
                const unsigned b0 = f2tf(Bs_s[(n0 + g) * 32 + k0i]);
                const unsigned b1 = f2tf(Bs_s[(n0 + g) * 32 + k1i]);
                mma_tf32(acc[0][j], ua[0], b0, b1);
                mma_tf32(acc[1][j], ua[1], b0, b1);
            }
        }

        mbar_arrive(mb + 24 + s * 8);
        if (tid == 0 && c + 3 < 32) {
            mbar_wait(mb + 24 + s * 8, (unsigned)(u & 1));
            mbar_expect_tx(mb + s * 8, TMA_ABYTES + TMA_BBYTES);
            tma2d(a_sb + s * TMA_ABYTES, &tmA, (c + 3) * 32, 0,      mb + s * 8);
            tma2d(b_sb + s * TMA_BBYTES, &tmB, (c + 3) * 32, n_base, mb + s * 8);
        }
    }

#pragma unroll
    for (int f = 0; f < 2; f++) {
        const int r0 = wm * 32 + f * 16 + g;
#pragma unroll
        for (int j = 0; j < 4; j++) {
            const int col = n_base + wn * 32 + j * 8 + tig * 2;
            const float4 v = acc[f][j];
            if (col + 1 < V_) {
                const float bv0 = bias[col], bv1 = bias[col + 1];
                C[(size_t)r0 * V_ + col]           = v.x + bv0;
                C[(size_t)r0 * V_ + col + 1]       = v.y + bv1;
                C[(size_t)(r0 + 8) * V_ + col]     = v.z + bv0;
                C[(size_t)(r0 + 8) * V_ + col + 1] = v.w + bv1;
            } else if (col < V_) {
                const float bv0 = bias[col];
                C[(size_t)r0 * V_ + col]       = v.x + bv0;
                C[(size_t)(r0 + 8) * V_ + col] = v.z + bv0;
            }
        }
    }
}

// ---------------------------------------------------------------------------
// Fallback (proven R6): cp.async 2-stage tf32 GEMM. Used only if the
// cuTensorMapEncodeTiled driver entry point is unavailable.
// ---------------------------------------------------------------------------
__global__ __launch_bounds__(256, 2) void out_gemm_tf32(
    const float* __restrict__ A, const float* __restrict__ Bw,
    const float* __restrict__ bias, float* __restrict__ C)
{
    __shared__ float As[2][64][20];
    __shared__ float Bs[2][128][20];
    const int tid = threadIdx.x;
    const int lane = tid & 31, warp = tid >> 5;
    const int g = lane >> 2, tig = lane & 3;
    const int wm = warp & 1, wn = warp >> 1;
    const int n_base = blockIdx.x * 128;

    const int srow = tid >> 2;
    const int sf   = (tid & 3) << 2;

    float4 acc[2][4];
#pragma unroll
    for (int f = 0; f < 2; f++)
#pragma unroll
        for (int j = 0; j < 4; j++) acc[f][j] = make_float4(0.f, 0.f, 0.f, 0.f);

#define STAGE(buf, ch) do {                                                        \
        cp_async16(&As[buf][srow][sf], A + (size_t)srow * 1024 + (ch) * 16 + sf);  \
        const int n0s = n_base + srow;                                             \
        if (n0s < V_)                                                              \
            cp_async16(&Bs[buf][srow][sf],                                         \
                       Bw + (size_t)n0s * 1024 + (ch) * 16 + sf);                  \
        const int n1s = n_base + 64 + srow;                                        \
        if (n1s < V_)                                                              \
            cp_async16(&Bs[buf][64 + srow][sf],                                    \
                       Bw + (size_t)n1s * 1024 + (ch) * 16 + sf);                  \
        cp_commit();                                                               \
    } while (0)

    STAGE(0, 0);

    for (int c = 0; c < 64; c++) {
        const int buf = c & 1;
        if (c < 63) { STAGE(buf ^ 1, c + 1); cp_wait<1>(); }
        else        { cp_wait<0>(); }
        __syncthreads();

#pragma unroll
        for (int s = 0; s < 2; s++) {
            const int ks = s * 8;
            unsigned ua[2][4];
#pragma unroll
            for (int f = 0; f < 2; f++) {
                const int m0 = wm * 32 + f * 16;
                ua[f][0] = f2tf(As[buf][m0 + g][ks + tig]);
                ua[f][1] = f2tf(As[buf][m0 + g + 8][ks + tig]);
                ua[f][2] = f2tf(As[buf][m0 + g][ks + tig + 4]);
                ua[f][3] = f2tf(As[buf][m0 + g + 8][ks + tig + 4]);
            }
#pragma unroll
            for (int j = 0; j < 4; j++) {
                const int n0 = wn * 32 + j * 8;
                const unsigned b0 = f2tf(Bs[buf][n0 + g][ks + tig]);
                const unsigned b1 = f2tf(Bs[buf][n0 + g][ks + tig + 4]);
                mma_tf32(acc[0][j], ua[0], b0, b1);
                mma_tf32(acc[1][j], ua[1], b0, b1);
            }
        }
        __syncthreads();
    }
#undef STAGE

#pragma unroll
    for (int f = 0; f < 2; f++) {
        const int r0 = wm * 32 + f * 16 + g;
#pragma unroll
        for (int j = 0; j < 4; j++) {
            const int col = n_base + wn * 32 + j * 8 + tig * 2;
            const float4 v = acc[f][j];
            if (col + 1 < V_) {
                const float bv0 = bias[col], bv1 = bias[col + 1];
                C[(size_t)r0 * V_ + col]           = v.x + bv0;
                C[(size_t)r0 * V_ + col + 1]       = v.y + bv1;
                C[(size_t)(r0 + 8) * V_ + col]     = v.z + bv0;
                C[(size_t)(r0 + 8) * V_ + col + 1] = v.w + bv1;
            } else if (col < V_) {
                const float bv0 = bias[col];
                C[(size_t)r0 * V_ + col]       = v.x + bv0;
                C[(size_t)(r0 + 8) * V_ + col] = v.z + bv0;
            }
        }
    }
}

// ---------------------------------------------------------------------------
// GRU gate math.
// ---------------------------------------------------------------------------
__global__ void gru_gates(const float* __restrict__ b_ih,
                          const float* __restrict__ b_hh,
                          const float* __restrict__ hprev,
                          float* __restrict__ out_hidden)
{
    const int idx = blockIdx.x * blockDim.x + threadIdx.x;   // < B*H
    const int b = idx >> 10, h = idx & (H_ - 1);
    float gir = b_ih[h], giz = b_ih[H_ + h], gin = b_ih[2 * H_ + h];
    float ghr = b_hh[h], ghz = b_hh[H_ + h], ghn = b_hh[2 * H_ + h];
#pragma unroll
    for (int p = 0; p < 4; p++) {
        const float* gi = g_gi_part + (size_t)p * (B_ * 3 * H_) + (size_t)b * 3 * H_;
        const float* gh = g_gh_part + (size_t)p * (B_ * 3 * H_) + (size_t)b * 3 * H_;
        gir += gi[h];          ghr += gh[h];
        giz += gi[H_ + h];     ghz += gh[H_ + h];
        gin += gi[2 * H_ + h]; ghn += gh[2 * H_ + h];
    }
    const float r = 1.f / (1.f + expf(-(gir + ghr)));
    const float z = 1.f / (1.f + expf(-(giz + ghz)));
    const float n = tanhf(gin + r * ghn);
    const float hn = (1.f - z) * n + z * hprev[idx];
    g_concat_in[(size_t)b * 2 * H_ + h] = hn;
    out_hidden[idx] = hn;
}

// ---------------------------------------------------------------------------
// Flash-style attention: one pass over encoder_outputs (512 MB), per-warp
// online softmax + register-resident H=1024 context accumulator.
// ---------------------------------------------------------------------------
__global__ __launch_bounds__(256, 1) void flash_attn(const float* __restrict__ enc)
{
    const int b = blockIdx.y;
    const int chunk = blockIdx.x;
    __shared__ float sh[H_];
    const int t = threadIdx.x;
    *(float4*)&sh[t * 4] = *(const float4*)&g_concat_in[(size_t)b * 2 * H_ + t * 4];
    __syncthreads();

    const int warp = t >> 5, lane = t & 31;
    float4 hn[8];
#pragma unroll
    for (int i = 0; i < 8; i++) hn[i] = *(const float4*)&sh[i * 128 + lane * 4];

    float m = -INFINITY, l = 0.f;
    float4 cv[8];
#pragma unroll
    for (int i = 0; i < 8; i++) cv[i] = make_float4(0.f, 0.f, 0.f, 0.f);

    const int sbase = chunk * 128 + warp * 16;
    for (int si = 0; si < 16; si++) {
        const int s = sbase + si;
        const float4* ep = (const float4*)(enc + ((size_t)s * B_ + b) * H_);
        float4 ev[8];
        float d = 0.f;
#pragma unroll
        for (int i = 0; i < 8; i++) {
            ev[i] = ep[i * 32 + lane];
            d = fmaf(ev[i].x, hn[i].x, d);
            d = fmaf(ev[i].y, hn[i].y, d);
            d = fmaf(ev[i].z, hn[i].z, d);
            d = fmaf(ev[i].w, hn[i].w, d);
        }
#pragma unroll
        for (int off = 16; off; off >>= 1)
            d += __shfl_xor_sync(0xffffffffu, d, off);

        if (lane == 0) g_energies[(size_t)b * S_ + s] = d;

        const float mn = fmaxf(m, d);
        const float sc = expf(m - mn);
        const float p  = expf(d - mn);
        l = l * sc + p;
#pragma unroll
        for (int i = 0; i < 8; i++) {
            cv[i].x = fmaf(p, ev[i].x, cv[i].x * sc);
            cv[i].y = fmaf(p, ev[i].y, cv[i].y * sc);
            cv[i].z = fmaf(p, ev[i].z, cv[i].z * sc);
            cv[i].w = fmaf(p, ev[i].w, cv[i].w * sc);
        }
        m = mn;
    }

    const int pi = chunk * 8 + warp;
    if (lane == 0) g_ml[b * 128 + pi] = make_float2(m, l);
    float4* cp = (float4*)(g_ctxp + ((size_t)(b * 128 + pi)) * H_);
#pragma unroll
    for (int i = 0; i < 8; i++) cp[i * 32 + lane] = cv[i];
}

// ---------------------------------------------------------------------------
// Combine softmax partials. grid = (4, B), 64 threads.
// ---------------------------------------------------------------------------
__global__ void attn_combine()
{
    const int b = blockIdx.y, q = blockIdx.x, t = threadIdx.x;  // t < 64
    __shared__ float sw[128];
    __shared__ float red[64];

    const float2 ml0 = g_ml[b * 128 + t];
    const float2 ml1 = g_ml[b * 128 + 64 + t];

    red[t] = fmaxf(ml0.x, ml1.x);
    __syncthreads();
    for (int off = 32; off >= 1; off >>= 1) {
        if (t < off) red[t] = fmaxf(red[t], red[t + off]);
        __syncthreads();
    }
    const float M = red[0];
    __syncthreads();

    const float w0 = expf(ml0.x - M), w1 = expf(ml1.x - M);
    sw[t] = w0; sw[64 + t] = w1;
    red[t] = ml0.y * w0 + ml1.y * w1;
    __syncthreads();
    for (int off = 32; off >= 1; off >>= 1) {
        if (t < off) red[t] += red[t + off];
        __syncthreads();
    }
    const float L = red[0];

    float4 acc = make_float4(0.f, 0.f, 0.f, 0.f);
    const float4* base = (const float4*)(g_ctxp + (size_t)b * 128 * H_) + q * 64 + t;
#pragma unroll 8
    for (int p = 0; p < 128; p++) {
        const float f = sw[p];
        const float4 v = base[(size_t)p * (H_ / 4)];
        acc.x = fmaf(f, v.x, acc.x);
        acc.y = fmaf(f, v.y, acc.y);
        acc.z = fmaf(f, v.z, acc.z);
        acc.w = fmaf(f, v.w, acc.w);
    }
    const float inv = 1.f / L;
    acc.x *= inv; acc.y *= inv; acc.z *= inv; acc.w *= inv;
    *(float4*)&g_concat_in[(size_t)b * 2 * H_ + H_ + (q * 64 + t) * 4] = acc;
    if (q == 0 && t == 0) { g_Mv[b] = M; g_Lv[b] = L; }
}

// attn_weights output
__global__ void attn_weights_out(float* __restrict__ out_attn)
{
    const int idx = blockIdx.x * blockDim.x + threadIdx.x;   // < B*S
    const int b = idx >> 11;
    out_attn[idx] = expf(g_energies[idx] - g_Mv[b]) / g_Lv[b];
}

// Sum concat-GEMM K-split partials, add bias, tanh.
__global__ void cat_finalize(const float* __restrict__ b_concat)
{
    const int idx = blockIdx.x * blockDim.x + threadIdx.x;   // < B*H
    float v = b_concat[idx & (H_ - 1)];
#pragma unroll
    for (int p = 0; p < 8; p++) v += g_cat_part[(size_t)p * (B_ * H_) + idx];
    g_concat_out[idx] = tanhf(v);
}

// ---------------------------------------------------------------------------
typedef CUresult (*PFN_encodeTiled)(
    CUtensorMap*, CUtensorMapDataType, cuuint32_t, void*,
    const cuuint64_t*, const cuuint64_t*, const cuuint32_t*, const cuuint32_t*,
    CUtensorMapInterleave, CUtensorMapSwizzle, CUtensorMapL2promotion,
    CUtensorMapFloatOOBfill);

extern "C" void kernel_launch(void* const* d_in, const int* in_sizes, int n_in,
                              void* d_out, int out_size)
{
    (void)in_sizes; (void)n_in; (void)out_size;
    const float* x    = (const float*)d_in[0];
    const float* h0   = (const float*)d_in[1];
    const float* enc  = (const float*)d_in[2];
    const float* w_ih = (const float*)d_in[3];
    const float* w_hh = (const float*)d_in[4];
    const float* b_ih = (const float*)d_in[5];
    const float* b_hh = (const float*)d_in[6];
    const float* Wc   = (const float*)d_in[7];
    const float* bc   = (const float*)d_in[8];
    const float* Wo   = (const float*)d_in[9];
    const float* bo   = (const float*)d_in[10];

    float* out        = (float*)d_out;
    float* out_output = out;                              // [B,V]
    float* out_hidden = out + (size_t)B_ * V_;            // [1,B,H]
    float* out_attn   = out_hidden + (size_t)B_ * H_;     // [B,1,S]

    void *p_gi, *p_gh, *p_cat, *p_cin, *p_cout;
    cudaGetSymbolAddress(&p_gi,  g_gi_part);
    cudaGetSymbolAddress(&p_gh,  g_gh_part);
    cudaGetSymbolAddress(&p_cat, g_cat_part);
    cudaGetSymbolAddress(&p_cin, g_concat_in);
    cudaGetSymbolAddress(&p_cout, g_concat_out);

    // GRU input/hidden GEMMs (K-split x4)
    gemm64<<<dim3(48, 4), 256>>>(x,  w_ih, (float*)p_gi, 3 * H_, E_, E_ / 4, nullptr, 0);
    gemm64<<<dim3(48, 4), 256>>>(h0, w_hh, (float*)p_gh, 3 * H_, H_, H_ / 4, nullptr, 0);
    gru_gates<<<(B_ * H_) / 256, 256>>>(b_ih, b_hh, h0, out_hidden);

    // One-pass attention + split-softmax combine
    flash_attn<<<dim3(16, B_), 256>>>(enc);
    attn_combine<<<dim3(4, B_), 64>>>();
    attn_weights_out<<<(B_ * S_) / 256, 256>>>(out_attn);

    // concat projection (K-split x8) + tanh
    gemm64<<<dim3(16, 8), 256>>>((const float*)p_cin, Wc, (float*)p_cat,
                                 H_, 2 * H_, 256, nullptr, 0);
    cat_finalize<<<(B_ * H_) / 256, 256>>>(bc);

    // Output GEMM via TMA (preferred) or cp.async fallback.
    PFN_encodeTiled enc_fn = nullptr;
    {
        void* fp = nullptr;
        cudaDriverEntryPointQueryResult qr = cudaDriverEntryPointSymbolNotFound;
        if (cudaGetDriverEntryPoint("cuTensorMapEncodeTiled", &fp,
                                    cudaEnableDefault, &qr) == cudaSuccess &&
            qr == cudaDriverEntryPointSuccess)
            enc_fn = (PFN_encodeTiled)fp;
    }

    bool tma_ok = false;
    if (enc_fn) {
        CUtensorMap tmA, tmB;
        cuuint64_t a_dims[2] = {1024, 64};
        cuuint64_t a_str[1]  = {1024 * sizeof(float)};
        cuuint32_t a_box[2]  = {32, 64};
        cuuint32_t ones[2]   = {1, 1};
        cuuint64_t b_dims[2] = {1024, V_};
        cuuint64_t b_str[1]  = {1024 * sizeof(float)};
        cuuint32_t b_box[2]  = {32, 128};
        CUresult r1 = enc_fn(&tmA, CU_TENSOR_MAP_DATA_TYPE_FLOAT32, 2, p_cout,
                             a_dims, a_str, a_box, ones,
                             CU_TENSOR_MAP_INTERLEAVE_NONE,
                             CU_TENSOR_MAP_SWIZZLE_128B,
                             CU_TENSOR_MAP_L2_PROMOTION_L2_128B,
                             CU_TENSOR_MAP_FLOAT_OOB_FILL_NONE);
        CUresult r2 = enc_fn(&tmB, CU_TENSOR_MAP_DATA_TYPE_FLOAT32, 2, (void*)Wo,
                             b_dims, b_str, b_box, ones,
                             CU_TENSOR_MAP_INTERLEAVE_NONE,
                             CU_TENSOR_MAP_SWIZZLE_128B,
                             CU_TENSOR_MAP_L2_PROMOTION_L2_128B,
                             CU_TENSOR_MAP_FLOAT_OOB_FILL_NONE);
        if (r1 == CUDA_SUCCESS && r2 == CUDA_SUCCESS) {
            cudaFuncSetAttribute(out_gemm_tma,
                                 cudaFuncAttributeMaxDynamicSharedMemorySize,
                                 TMA_SMEM);
            out_gemm_tma<<<(V_ + 127) / 128, 256, TMA_SMEM>>>(tmA, tmB, bo, out_output);
            tma_ok = true;
        }
    }
    if (!tma_ok)
        out_gemm_tf32<<<(V_ + 127) / 128, 256>>>((const float*)p_cout, Wo, bo, out_output);
}